// round 3
// baseline (speedup 1.0000x reference)
#include <cuda_runtime.h>
#include <math.h>

// ---------------------------------------------------------------------------
// BNAF forward: D=8, H=512, B=2048, 4 masked layers + tanh, with log-det flow.
//
// Key identity: on the diagonal blocks, exp(ld) == w (the normalized weight),
// so logsumexp(sld^T + ld) == m + log( exp(sld - m) . w_diag ), turning the
// per-pair exp into a plain dot product.
// ---------------------------------------------------------------------------

#define B_  2048
#define H_  512
#define D_  8

// scratch (device globals; no allocation allowed)
__device__ float g_wT1[8 * 512];     // [in][out]
__device__ float g_wT2[512 * 512];
__device__ float g_wT3[512 * 512];
__device__ float g_wT4[512 * 8];
__device__ float g_h1[B_ * H_];
__device__ float g_h2[B_ * H_];
__device__ float g_h3[B_ * H_];
__device__ float g_t2[B_ * H_];
__device__ float g_t3[B_ * H_];
__device__ float g_t4[B_ * D_];
__device__ float g_sldA[B_ * H_];    // [b][i*64+o]
__device__ float g_sldB[B_ * H_];

__device__ __forceinline__ float ldtanh(float y) {
    // -2*(y - log2 + softplus(-2y)), stable softplus
    float z  = -2.0f * y;
    float sp = fmaxf(z, 0.0f) + log1pf(expf(-fabsf(z)));
    return -2.0f * (y - 0.69314718055994530942f + sp);
}

// ---------------------------------------------------------------------------
// prep: build normalized transposed weights wT[in][out] for one layer.
// v = exp(W)*mask_d + W*mask_o ; w = exp(logg) * v / ||v||_row
// ---------------------------------------------------------------------------
__global__ void prep_kernel(const float* __restrict__ W,
                            const float* __restrict__ logg, int layer) {
    float* wT; int IN, OUT, ib, ob;
    if      (layer == 1) { wT = g_wT1; IN = 8;   OUT = 512; ib = 1;  ob = 64; }
    else if (layer == 2) { wT = g_wT2; IN = 512; OUT = 512; ib = 64; ob = 64; }
    else if (layer == 3) { wT = g_wT3; IN = 512; OUT = 512; ib = 64; ob = 64; }
    else                 { wT = g_wT4; IN = 512; OUT = 8;   ib = 64; ob = 1;  }

    int o = blockIdx.x * blockDim.y + threadIdx.y;
    if (o >= OUT) return;
    int lane = threadIdx.x;
    int i = o / ob;

    float sq = 0.0f;
    for (int c = lane; c < IN; c += 32) {
        int jb = c / ib;
        float wv = W[o * IN + c];
        float v  = (jb == i) ? expf(wv) : (jb < i ? wv : 0.0f);
        sq += v * v;
    }
    #pragma unroll
    for (int off = 16; off; off >>= 1)
        sq += __shfl_xor_sync(0xffffffffu, sq, off);

    float scale = expf(logg[o]) / sqrtf(sq);
    for (int c = lane; c < IN; c += 32) {
        int jb = c / ib;
        float wv = W[o * IN + c];
        float v  = (jb == i) ? expf(wv) : (jb < i ? wv : 0.0f);
        wT[c * OUT + o] = v * scale;
    }
}

// ---------------------------------------------------------------------------
// layer 1: y = x @ w1^T + b1 (K=8), h1 = tanh(y),
// fused sld init: sld1[b, og] = log(w1_diag[og]) + ldtanh(y)
// ---------------------------------------------------------------------------
__global__ void gemm1_kernel(const float* __restrict__ x,
                             const float* __restrict__ bias) {
    __shared__ float xs[8];
    int b = blockIdx.x, og = threadIdx.x;
    if (og < 8) xs[og] = x[b * 8 + og];
    __syncthreads();

    float acc = bias[og];
    #pragma unroll
    for (int k = 0; k < 8; k++) acc += xs[k] * g_wT1[k * 512 + og];

    float h = tanhf(acc);
    float t = ldtanh(acc);
    g_h1[b * 512 + og]   = h;
    g_sldA[b * 512 + og] = logf(g_wT1[(og >> 6) * 512 + og]) + t;
}

// ---------------------------------------------------------------------------
// middle GEMM (layers 2,3): C[2048x512] = A[2048x512] @ wT[512x512] + bias,
// h = tanh, t = ldtanh. Exploits block-lower-triangular mask: for the n-tile
// covering block i, only k < (i+1)*64 is nonzero (exact — weights are 0 above).
// BM=BN=64, BK=16, 256 threads, 4x4 per thread.
// ---------------------------------------------------------------------------
__global__ void gemm_mid_kernel(int layer, const float* __restrict__ bias) {
    const float* A   = (layer == 2) ? g_h1  : g_h2;
    const float* wT  = (layer == 2) ? g_wT2 : g_wT3;
    float*       Hout = (layer == 2) ? g_h2 : g_h3;
    float*       Tout = (layer == 2) ? g_t2 : g_t3;

    __shared__ float As[16][64];
    __shared__ float Bs[16][64];

    int n0 = blockIdx.x * 64, m0 = blockIdx.y * 64;
    int kmax = (blockIdx.x + 1) * 64;   // masked-structure skip
    int tid = threadIdx.x;
    int tx = tid & 15, ty = tid >> 4;

    int am = tid >> 2, ak = (tid & 3) * 4;
    int bk = tid >> 4, bn = (tid & 15) * 4;

    float acc[4][4] = {};

    for (int k0 = 0; k0 < kmax; k0 += 16) {
        float4 av = *(const float4*)(A + (m0 + am) * 512 + k0 + ak);
        As[ak + 0][am] = av.x; As[ak + 1][am] = av.y;
        As[ak + 2][am] = av.z; As[ak + 3][am] = av.w;
        *(float4*)(&Bs[bk][bn]) =
            *(const float4*)(wT + (k0 + bk) * 512 + n0 + bn);
        __syncthreads();

        #pragma unroll
        for (int k = 0; k < 16; k++) {
            float4 a  = *(const float4*)(&As[k][ty * 4]);
            float4 bq = *(const float4*)(&Bs[k][tx * 4]);
            acc[0][0] += a.x * bq.x; acc[0][1] += a.x * bq.y;
            acc[0][2] += a.x * bq.z; acc[0][3] += a.x * bq.w;
            acc[1][0] += a.y * bq.x; acc[1][1] += a.y * bq.y;
            acc[1][2] += a.y * bq.z; acc[1][3] += a.y * bq.w;
            acc[2][0] += a.z * bq.x; acc[2][1] += a.z * bq.y;
            acc[2][2] += a.z * bq.z; acc[2][3] += a.z * bq.w;
            acc[3][0] += a.w * bq.x; acc[3][1] += a.w * bq.y;
            acc[3][2] += a.w * bq.z; acc[3][3] += a.w * bq.w;
        }
        __syncthreads();
    }

    #pragma unroll
    for (int i = 0; i < 4; i++) {
        int m = m0 + ty * 4 + i;
        #pragma unroll
        for (int j = 0; j < 4; j++) {
            int n = n0 + tx * 4 + j;
            float y = acc[i][j] + bias[n];
            Hout[m * 512 + n] = tanhf(y);
            Tout[m * 512 + n] = ldtanh(y);
        }
    }
}

// ---------------------------------------------------------------------------
// middle sld (layers 2,3): per (b, i):
//   m = max_j sld_in[b,i,j]; p = exp(sld_in - m)
//   sld_out[b,i,o] = m + log( sum_j p[j] * w_diag[i][o][j] ) + t[b, i*64+o]
// One CTA per (i, 64-batch chunk); diag block cached in smem; warp per row.
// ---------------------------------------------------------------------------
__global__ void sld_mid_kernel(int layer) {
    const float* wT  = (layer == 2) ? g_wT2 : g_wT3;
    const float* sin_ = (layer == 2) ? g_sldA : g_sldB;
    float*       sout = (layer == 2) ? g_sldB : g_sldA;
    const float* T   = (layer == 2) ? g_t2 : g_t3;

    int i  = blockIdx.y;
    int b0 = blockIdx.x * 64;
    __shared__ float wd[64][65];          // wd[o][j]
    int tid = threadIdx.x;

    for (int idx = tid; idx < 4096; idx += 256) {
        int o = idx & 63, j = idx >> 6;
        wd[o][j] = wT[(i * 64 + j) * 512 + i * 64 + o];
    }
    __syncthreads();

    int warp = tid >> 5, lane = tid & 31;
    for (int it = 0; it < 8; ++it) {
        int b = b0 + warp * 8 + it;
        const float* sp = sin_ + b * 512 + i * 64;
        float s0 = sp[lane], s1 = sp[lane + 32];
        float m = fmaxf(s0, s1);
        #pragma unroll
        for (int off = 16; off; off >>= 1)
            m = fmaxf(m, __shfl_xor_sync(0xffffffffu, m, off));
        float p0 = expf(s0 - m), p1 = expf(s1 - m);

        float a0 = 0.0f, a1 = 0.0f;
        #pragma unroll
        for (int l2 = 0; l2 < 32; l2++) {
            float q0 = __shfl_sync(0xffffffffu, p0, l2);
            float q1 = __shfl_sync(0xffffffffu, p1, l2);
            a0 += q0 * wd[lane][l2]      + q1 * wd[lane][l2 + 32];
            a1 += q0 * wd[lane + 32][l2] + q1 * wd[lane + 32][l2 + 32];
        }
        float* op = sout + b * 512 + i * 64;
        const float* tp = T + b * 512 + i * 64;
        op[lane]      = m + logf(a0) + tp[lane];
        op[lane + 32] = m + logf(a1) + tp[lane + 32];
    }
}

// ---------------------------------------------------------------------------
// layer 4 GEMM: y4[b,o] = h3[b,:] . w4[o,:] + b4 (o<8), h=tanh -> d_out[0:16384]
// one warp per batch row
// ---------------------------------------------------------------------------
__global__ void gemm4_kernel(const float* __restrict__ bias,
                             float* __restrict__ out) {
    int warp = threadIdx.x >> 5, lane = threadIdx.x & 31;
    int b = blockIdx.x * 8 + warp;

    float acc[8] = {};
    for (int k = lane; k < 512; k += 32) {
        float hv = g_h3[b * 512 + k];
        const float4* wp = (const float4*)(g_wT4 + k * 8);
        float4 w0 = wp[0], w1 = wp[1];
        acc[0] += hv * w0.x; acc[1] += hv * w0.y;
        acc[2] += hv * w0.z; acc[3] += hv * w0.w;
        acc[4] += hv * w1.x; acc[5] += hv * w1.y;
        acc[6] += hv * w1.z; acc[7] += hv * w1.w;
    }
    #pragma unroll
    for (int o = 0; o < 8; o++)
        #pragma unroll
        for (int off = 16; off; off >>= 1)
            acc[o] += __shfl_xor_sync(0xffffffffu, acc[o], off);

    if (lane == 0) {
        #pragma unroll
        for (int o = 0; o < 8; o++) {
            float y = acc[o] + bias[o];
            out[b * 8 + o]  = tanhf(y);
            g_t4[b * 8 + o] = ldtanh(y);
        }
    }
}

// ---------------------------------------------------------------------------
// final sld (layer 4, ob=1): per (b,i):
//   d_out[16384 + b*8+i] = m + log( sum_j p[j]*w4_diag[i][j] ) + t4[b,i]
// one warp per (b,i)
// ---------------------------------------------------------------------------
__global__ void sld4_kernel(float* __restrict__ out) {
    int i = threadIdx.x >> 5, lane = threadIdx.x & 31;
    int b = blockIdx.x;
    const float* sp = g_sldA + b * 512 + i * 64;
    float s0 = sp[lane], s1 = sp[lane + 32];
    float m = fmaxf(s0, s1);
    #pragma unroll
    for (int off = 16; off; off >>= 1)
        m = fmaxf(m, __shfl_xor_sync(0xffffffffu, m, off));
    float p0 = expf(s0 - m), p1 = expf(s1 - m);
    float w0 = g_wT4[(i * 64 + lane) * 8 + i];
    float w1 = g_wT4[(i * 64 + lane + 32) * 8 + i];
    float a = p0 * w0 + p1 * w1;
    #pragma unroll
    for (int off = 16; off; off >>= 1)
        a += __shfl_xor_sync(0xffffffffu, a, off);
    if (lane == 0)
        out[B_ * D_ + b * 8 + i] = m + logf(a) + g_t4[b * 8 + i];
}

// ---------------------------------------------------------------------------
extern "C" void kernel_launch(void* const* d_in, const int* in_sizes, int n_in,
                              void* d_out, int out_size) {
    (void)in_sizes; (void)n_in; (void)out_size;
    const float* x  = (const float*)d_in[0];
    const float* W1 = (const float*)d_in[1];
    const float* g1 = (const float*)d_in[2];
    const float* b1 = (const float*)d_in[3];
    const float* W2 = (const float*)d_in[4];
    const float* g2 = (const float*)d_in[5];
    const float* b2 = (const float*)d_in[6];
    const float* W3 = (const float*)d_in[7];
    const float* g3 = (const float*)d_in[8];
    const float* b3 = (const float*)d_in[9];
    const float* W4 = (const float*)d_in[10];
    const float* g4 = (const float*)d_in[11];
    const float* b4 = (const float*)d_in[12];
    float* out = (float*)d_out;

    dim3 pb(32, 8);
    prep_kernel<<<64, pb>>>(W1, g1, 1);
    prep_kernel<<<64, pb>>>(W2, g2, 2);
    prep_kernel<<<64, pb>>>(W3, g3, 3);
    prep_kernel<<<1,  pb>>>(W4, g4, 4);

    gemm1_kernel<<<2048, 512>>>(x, b1);

    gemm_mid_kernel<<<dim3(8, 32), 256>>>(2, b2);
    sld_mid_kernel<<<dim3(32, 8), 256>>>(2);

    gemm_mid_kernel<<<dim3(8, 32), 256>>>(3, b3);
    sld_mid_kernel<<<dim3(32, 8), 256>>>(3);

    gemm4_kernel<<<256, 256>>>(b4, out);
    sld4_kernel<<<2048, 256>>>(out);
}

// round 4
// speedup vs baseline: 1.3786x; 1.3786x over previous
#include <cuda_runtime.h>
#include <math.h>

// ---------------------------------------------------------------------------
// BNAF forward: D=8, H=512, B=2048, 4 masked layers + tanh, with log-det flow.
//
// Identities used:
//  * diag-block exp(ld) == normalized weight w  =>  logsumexp(sld + ld) =
//      m + log( exp(sld-m) . w_diag )   (plain dot product, no per-pair exp)
//  * with E = exp(-2|y|), r = 1/(1+E):
//      tanh(y)   = sign(y) * (1-E) * r
//      ld(y)     = 2*ln2 - 2|y| + log(r^2)
//    and the layer's sld update collapses to ONE logf:
//      sld_out = m + 2*ln2 - 2|y| + log( Q * r^2 )
// ---------------------------------------------------------------------------

#define B_  2048
#define H_  512
#define D_  8
#define TWO_LN2 1.38629436111989062f

// scratch (device globals; no allocation allowed)
__device__ float g_wT1[8 * 512];      // [in][out]
__device__ float g_wT2[512 * 512];    // [in][out]
__device__ float g_wT3[512 * 512];    // [in][out]
__device__ float g_w4n[8 * 512];      // [out][in] (natural)
__device__ float g_logw1d[512];
__device__ float g_h1[B_ * H_];
__device__ float g_h2[B_ * H_];
__device__ float g_h3[B_ * H_];
__device__ float g_sldA[B_ * H_];     // [b][i*64+o]
__device__ float g_sldB[B_ * H_];

// ---------------------------------------------------------------------------
// merged prep: all 4 layers in ONE launch.
// v = exp(W)*mask_d + W*mask_o ; w = exp(logg) * v / ||v||_row
// layers 1-3 stored transposed [in][out]; layer 4 natural [out][in].
// ---------------------------------------------------------------------------
__global__ void prep_all_kernel(const float* __restrict__ W1, const float* __restrict__ g1,
                                const float* __restrict__ W2, const float* __restrict__ g2,
                                const float* __restrict__ W3, const float* __restrict__ g3,
                                const float* __restrict__ W4, const float* __restrict__ g4) {
    int blk = blockIdx.x;
    const float *W, *logg; int IN, OUT, ibshift, ob, layer, row0;
    if (blk < 64)       { layer = 1; W = W1; logg = g1; IN = 8;   OUT = 512; ibshift = 0; ob = 64; row0 = blk * 8; }
    else if (blk < 128) { layer = 2; W = W2; logg = g2; IN = 512; OUT = 512; ibshift = 6; ob = 64; row0 = (blk - 64) * 8; }
    else if (blk < 192) { layer = 3; W = W3; logg = g3; IN = 512; OUT = 512; ibshift = 6; ob = 64; row0 = (blk - 128) * 8; }
    else                { layer = 4; W = W4; logg = g4; IN = 512; OUT = 8;   ibshift = 6; ob = 1;  row0 = 0; }

    int o = row0 + threadIdx.y;
    if (o >= OUT) return;
    int lane = threadIdx.x;
    int i = o / ob;

    float sq = 0.0f;
    for (int c = lane; c < IN; c += 32) {
        int jb = c >> ibshift;
        float wv = W[o * IN + c];
        float v  = (jb == i) ? expf(wv) : (jb < i ? wv : 0.0f);
        sq += v * v;
    }
    #pragma unroll
    for (int off = 16; off; off >>= 1)
        sq += __shfl_xor_sync(0xffffffffu, sq, off);

    float scale = expf(logg[o]) / sqrtf(sq);
    for (int c = lane; c < IN; c += 32) {
        int jb = c >> ibshift;
        float wv = W[o * IN + c];
        float v  = (jb == i) ? expf(wv) : (jb < i ? wv : 0.0f);
        float w  = v * scale;
        if (layer == 1) {
            g_wT1[c * 512 + o] = w;
            if (c == i) g_logw1d[o] = logf(w);   // diag col for layer1 is c==i
        } else if (layer == 2) {
            g_wT2[c * 512 + o] = w;
        } else if (layer == 3) {
            g_wT3[c * 512 + o] = w;
        } else {
            g_w4n[o * 512 + c] = w;              // natural, coalesced
        }
    }
}

// ---------------------------------------------------------------------------
// layer 1: y = x @ w1^T + b1 (K=8), h1 = tanh(y), sld init fused.
// ---------------------------------------------------------------------------
__global__ void gemm1_kernel(const float* __restrict__ x,
                             const float* __restrict__ bias) {
    __shared__ float xs[8];
    int b = blockIdx.x, og = threadIdx.x;
    if (og < 8) xs[og] = x[b * 8 + og];
    __syncthreads();

    float acc = bias[og];
    #pragma unroll
    for (int k = 0; k < 8; k++) acc += xs[k] * g_wT1[k * 512 + og];

    float ay = fabsf(acc);
    float E  = expf(-2.0f * ay);
    float r  = 1.0f / (1.0f + E);
    g_h1[b * 512 + og]   = copysignf((1.0f - E) * r, acc);
    g_sldA[b * 512 + og] = g_logw1d[og] + TWO_LN2 - 2.0f * ay + logf(r * r);
}

// ---------------------------------------------------------------------------
// fused middle layer (2,3): masked GEMM + tanh + full sld logsumexp update.
// BM=BN=64, BK=16, 256 threads, 4x4/thread. n-block i only needs k < (i+1)*64.
// The diagonal weight block == the Bs tiles at k0 >= n0 (stashed to wdS).
// Epilogue: rowmax -> P=exp(s-m) -> Q = P @ wd^T (in-smem 64x64x64 GEMM)
//           -> sld_out = m + 2ln2 - 2|y| + log(Q*r^2); h = tanh via E,r.
// ---------------------------------------------------------------------------
__global__ void layer_mid_kernel(int layer, const float* __restrict__ bias) {
    const float* A    = (layer == 2) ? g_h1  : g_h2;
    const float* wT   = (layer == 2) ? g_wT2 : g_wT3;
    float*       Hout = (layer == 2) ? g_h2  : g_h3;
    const float* Sin  = (layer == 2) ? g_sldA : g_sldB;
    float*       Sout = (layer == 2) ? g_sldB : g_sldA;

    __shared__ float As[16][64];
    __shared__ float Bs[16][64];
    __shared__ float wdS[64][68];   // [j][o] diagonal block (= Bs layout)
    __shared__ float Ps[64][68];    // [j][m] exp(sld - m)
    __shared__ float pm[64][4];
    __shared__ float mrow[64];

    int n0 = blockIdx.x * 64, m0 = blockIdx.y * 64;
    int kmax = n0 + 64;             // masked-structure skip
    int tid = threadIdx.x;
    int tx = tid & 15, ty = tid >> 4;

    int am = tid >> 2, ak = (tid & 3) * 4;
    int bk = tid >> 4, bn = (tid & 15) * 4;

    float acc[4][4] = {};

    for (int k0 = 0; k0 < kmax; k0 += 16) {
        float4 av = *(const float4*)(A + (m0 + am) * 512 + k0 + ak);
        float4 bv = *(const float4*)(wT + (k0 + bk) * 512 + n0 + bn);
        As[ak + 0][am] = av.x; As[ak + 1][am] = av.y;
        As[ak + 2][am] = av.z; As[ak + 3][am] = av.w;
        *(float4*)(&Bs[bk][bn]) = bv;
        if (k0 >= n0)                               // diagonal block tiles
            *(float4*)(&wdS[k0 - n0 + bk][bn]) = bv;
        __syncthreads();

        #pragma unroll
        for (int k = 0; k < 16; k++) {
            float4 a  = *(const float4*)(&As[k][ty * 4]);
            float4 bq = *(const float4*)(&Bs[k][tx * 4]);
            acc[0][0] += a.x * bq.x; acc[0][1] += a.x * bq.y;
            acc[0][2] += a.x * bq.z; acc[0][3] += a.x * bq.w;
            acc[1][0] += a.y * bq.x; acc[1][1] += a.y * bq.y;
            acc[1][2] += a.y * bq.z; acc[1][3] += a.y * bq.w;
            acc[2][0] += a.z * bq.x; acc[2][1] += a.z * bq.y;
            acc[2][2] += a.z * bq.z; acc[2][3] += a.z * bq.w;
            acc[3][0] += a.w * bq.x; acc[3][1] += a.w * bq.y;
            acc[3][2] += a.w * bq.z; acc[3][3] += a.w * bq.w;
        }
        __syncthreads();
    }

    // ---- sld tile load + row max ----
    int row = tid >> 2, q = tid & 3;
    const float4* sp = (const float4*)(Sin + (m0 + row) * 512 + n0 + q * 16);
    float4 v4[4];
    float mx = -1e30f;
    #pragma unroll
    for (int c = 0; c < 4; c++) {
        v4[c] = sp[c];
        mx = fmaxf(mx, fmaxf(fmaxf(v4[c].x, v4[c].y), fmaxf(v4[c].z, v4[c].w)));
    }
    pm[row][q] = mx;
    __syncthreads();
    if (tid < 64)
        mrow[tid] = fmaxf(fmaxf(pm[tid][0], pm[tid][1]),
                          fmaxf(pm[tid][2], pm[tid][3]));
    __syncthreads();

    // ---- exponentiate into Ps[j][m] (transposed for the mini-GEMM) ----
    {
        float m = mrow[row];
        #pragma unroll
        for (int c = 0; c < 4; c++) {
            int j = q * 16 + c * 4;
            Ps[j + 0][row] = expf(v4[c].x - m);
            Ps[j + 1][row] = expf(v4[c].y - m);
            Ps[j + 2][row] = expf(v4[c].z - m);
            Ps[j + 3][row] = expf(v4[c].w - m);
        }
    }
    __syncthreads();

    // ---- mini-GEMM: Q[m][o] = sum_j P[m][j] * wd[o][j] ----
    float qacc[4][4] = {};
    #pragma unroll 8
    for (int j = 0; j < 64; j++) {
        float4 a  = *(const float4*)(&Ps[j][ty * 4]);
        float4 bq = *(const float4*)(&wdS[j][tx * 4]);
        qacc[0][0] += a.x * bq.x; qacc[0][1] += a.x * bq.y;
        qacc[0][2] += a.x * bq.z; qacc[0][3] += a.x * bq.w;
        qacc[1][0] += a.y * bq.x; qacc[1][1] += a.y * bq.y;
        qacc[1][2] += a.y * bq.z; qacc[1][3] += a.y * bq.w;
        qacc[2][0] += a.z * bq.x; qacc[2][1] += a.z * bq.y;
        qacc[2][2] += a.z * bq.z; qacc[2][3] += a.z * bq.w;
        qacc[3][0] += a.w * bq.x; qacc[3][1] += a.w * bq.y;
        qacc[3][2] += a.w * bq.z; qacc[3][3] += a.w * bq.w;
    }

    // ---- epilogue: h = tanh(y), sld_out in one logf ----
    #pragma unroll
    for (int ii = 0; ii < 4; ii++) {
        int m = m0 + ty * 4 + ii;
        float mr = mrow[ty * 4 + ii];
        #pragma unroll
        for (int jj = 0; jj < 4; jj++) {
            int n = n0 + tx * 4 + jj;
            float y  = acc[ii][jj] + bias[n];
            float ay = fabsf(y);
            float E  = expf(-2.0f * ay);
            float r  = 1.0f / (1.0f + E);
            Hout[m * 512 + n] = copysignf((1.0f - E) * r, y);
            Sout[m * 512 + n] = mr + TWO_LN2 - 2.0f * ay
                              + logf(qacc[ii][jj] * r * r);
        }
    }
}

// ---------------------------------------------------------------------------
// fused layer 4: block per batch row; warp i handles data dim i.
// GEMM (512-dot) + tanh -> out[0:16384]; sld finale -> out[16384:32768].
// ---------------------------------------------------------------------------
__global__ void layer_last_kernel(const float* __restrict__ bias,
                                  float* __restrict__ out) {
    __shared__ float hs[512];
    int b = blockIdx.x, tid = threadIdx.x;
    hs[tid]       = g_h3[b * 512 + tid];
    hs[tid + 256] = g_h3[b * 512 + tid + 256];
    __syncthreads();

    int i = tid >> 5, lane = tid & 31;

    float acc = 0.0f;
    const float* wr = g_w4n + i * 512;
    #pragma unroll 4
    for (int k = lane; k < 512; k += 32) acc += hs[k] * wr[k];
    #pragma unroll
    for (int off = 16; off; off >>= 1)
        acc += __shfl_xor_sync(0xffffffffu, acc, off);

    float y  = acc + bias[i];
    float ay = fabsf(y);
    float E  = expf(-2.0f * ay);
    float r  = 1.0f / (1.0f + E);

    // sld finale for (b, i)
    const float* sp = g_sldA + b * 512 + i * 64;
    float s0 = sp[lane], s1 = sp[lane + 32];
    float m = fmaxf(s0, s1);
    #pragma unroll
    for (int off = 16; off; off >>= 1)
        m = fmaxf(m, __shfl_xor_sync(0xffffffffu, m, off));
    float p0 = expf(s0 - m), p1 = expf(s1 - m);
    float w0 = g_w4n[i * 512 + i * 64 + lane];
    float w1 = g_w4n[i * 512 + i * 64 + lane + 32];
    float a = p0 * w0 + p1 * w1;
    #pragma unroll
    for (int off = 16; off; off >>= 1)
        a += __shfl_xor_sync(0xffffffffu, a, off);

    if (lane == 0) {
        out[b * 8 + i]           = copysignf((1.0f - E) * r, y);
        out[B_ * D_ + b * 8 + i] = m + TWO_LN2 - 2.0f * ay + logf(a * r * r);
    }
}

// ---------------------------------------------------------------------------
extern "C" void kernel_launch(void* const* d_in, const int* in_sizes, int n_in,
                              void* d_out, int out_size) {
    (void)in_sizes; (void)n_in; (void)out_size;
    const float* x  = (const float*)d_in[0];
    const float* W1 = (const float*)d_in[1];
    const float* g1 = (const float*)d_in[2];
    const float* b1 = (const float*)d_in[3];
    const float* W2 = (const float*)d_in[4];
    const float* g2 = (const float*)d_in[5];
    const float* b2 = (const float*)d_in[6];
    const float* W3 = (const float*)d_in[7];
    const float* g3 = (const float*)d_in[8];
    const float* b3 = (const float*)d_in[9];
    const float* W4 = (const float*)d_in[10];
    const float* g4 = (const float*)d_in[11];
    const float* b4 = (const float*)d_in[12];
    float* out = (float*)d_out;

    prep_all_kernel<<<193, dim3(32, 8)>>>(W1, g1, W2, g2, W3, g3, W4, g4);
    gemm1_kernel<<<2048, 512>>>(x, b1);
    layer_mid_kernel<<<dim3(8, 32), 256>>>(2, b2);
    layer_mid_kernel<<<dim3(8, 32), 256>>>(3, b3);
    layer_last_kernel<<<2048, 256>>>(b4, out);
}

// round 6
// speedup vs baseline: 1.8202x; 1.3204x over previous
#include <cuda_runtime.h>
#include <math.h>

// ---------------------------------------------------------------------------
// BNAF forward: D=8, H=512, B=2048, 4 masked layers + tanh, with log-det flow.
//
// Identities used:
//  * diag-block exp(ld) == normalized weight w  =>  logsumexp(sld + ld) =
//      m + log( exp(sld-m) . w_diag )   (plain dot product, no per-pair exp)
//  * with E = exp(-2|y|), r = 1/(1+E):
//      tanh(y) = sign(y)*(1-E)*r ;  sld_out = m + 2ln2 - 2|y| + log(Q*r^2)
// ---------------------------------------------------------------------------

#define B_  2048
#define H_  512
#define D_  8
#define TWO_LN2 1.38629436111989062f
#define NSM 152          // persistent grid size for layer_mid

// scratch (device globals; no allocation allowed)
__device__ float g_wT1[8 * 512];      // [in][out]
__device__ float g_wT2[512 * 512];    // [in][out]
__device__ float g_wT3[512 * 512];    // [in][out]
__device__ float g_w4n[8 * 512];      // [out][in] (natural)
__device__ float g_logw1d[512];
__device__ float g_h1[B_ * H_];
__device__ float g_h2[B_ * H_];
__device__ float g_h3[B_ * H_];
__device__ float g_sldA[B_ * H_];     // [b][i*64+o]
__device__ float g_sldB[B_ * H_];

// ---------------------------------------------------------------------------
// merged prep: all 4 layers in ONE launch.
// ---------------------------------------------------------------------------
__global__ void prep_all_kernel(const float* __restrict__ W1, const float* __restrict__ g1,
                                const float* __restrict__ W2, const float* __restrict__ g2,
                                const float* __restrict__ W3, const float* __restrict__ g3,
                                const float* __restrict__ W4, const float* __restrict__ g4) {
    int blk = blockIdx.x;
    const float *W, *logg; int IN, OUT, ibshift, ob, layer, row0;
    if (blk < 64)       { layer = 1; W = W1; logg = g1; IN = 8;   OUT = 512; ibshift = 0; ob = 64; row0 = blk * 8; }
    else if (blk < 128) { layer = 2; W = W2; logg = g2; IN = 512; OUT = 512; ibshift = 6; ob = 64; row0 = (blk - 64) * 8; }
    else if (blk < 192) { layer = 3; W = W3; logg = g3; IN = 512; OUT = 512; ibshift = 6; ob = 64; row0 = (blk - 128) * 8; }
    else                { layer = 4; W = W4; logg = g4; IN = 512; OUT = 8;   ibshift = 6; ob = 1;  row0 = 0; }

    int o = row0 + threadIdx.y;
    if (o >= OUT) return;
    int lane = threadIdx.x;
    int i = o / ob;

    float sq = 0.0f;
    for (int c = lane; c < IN; c += 32) {
        int jb = c >> ibshift;
        float wv = W[o * IN + c];
        float v  = (jb == i) ? expf(wv) : (jb < i ? wv : 0.0f);
        sq += v * v;
    }
    #pragma unroll
    for (int off = 16; off; off >>= 1)
        sq += __shfl_xor_sync(0xffffffffu, sq, off);

    float scale = expf(logg[o]) / sqrtf(sq);
    for (int c = lane; c < IN; c += 32) {
        int jb = c >> ibshift;
        float wv = W[o * IN + c];
        float v  = (jb == i) ? expf(wv) : (jb < i ? wv : 0.0f);
        float w  = v * scale;
        if (layer == 1) {
            g_wT1[c * 512 + o] = w;
            if (c == i) g_logw1d[o] = logf(w);
        } else if (layer == 2) {
            g_wT2[c * 512 + o] = w;
        } else if (layer == 3) {
            g_wT3[c * 512 + o] = w;
        } else {
            g_w4n[o * 512 + c] = w;
        }
    }
}

// ---------------------------------------------------------------------------
// layer 1: per block 8 batch rows; weight column cached in registers.
// ---------------------------------------------------------------------------
__global__ void gemm1_kernel(const float* __restrict__ x,
                             const float* __restrict__ bias) {
    __shared__ float xs[8][8];
    int og = threadIdx.x;
    int b0 = blockIdx.x * 8;

    float w[8];
    #pragma unroll
    for (int k = 0; k < 8; k++) w[k] = g_wT1[k * 512 + og];
    float lw = g_logw1d[og];
    float bz = bias[og];

    if (og < 64) xs[og >> 3][og & 7] = x[b0 * 8 + og];
    __syncthreads();

    #pragma unroll
    for (int r = 0; r < 8; r++) {
        float acc = bz;
        #pragma unroll
        for (int k = 0; k < 8; k++) acc += w[k] * xs[r][k];
        float ay = fabsf(acc);
        float E  = expf(-2.0f * ay);
        float rc = 1.0f / (1.0f + E);
        int b = b0 + r;
        g_h1[b * 512 + og]   = copysignf((1.0f - E) * rc, acc);
        g_sldA[b * 512 + og] = lw + TWO_LN2 - 2.0f * ay + logf(rc * rc);
    }
}

// ---------------------------------------------------------------------------
// fused middle layer (2,3): persistent worklist + double-buffered masked GEMM
// + tanh + sld logsumexp update. BM=BN=64, BK=32, 256 threads, 4x4/thread.
// Item t (0..255): i = 7 - (t>>5) [heaviest first], m-block = t & 31.
// Serpentine schedule over grid=NSM balances per-SM work to ~9.3 k-tiles.
// Smem union: As/Bs double buffers alias epilogue's Ps/wdS (17KB + 17KB).
// ---------------------------------------------------------------------------
__global__ __launch_bounds__(256) void layer_mid_kernel(int layer,
                                                        const float* __restrict__ bias) {
    const float* A    = (layer == 2) ? g_h1  : g_h2;
    const float* wT   = (layer == 2) ? g_wT2 : g_wT3;
    float*       Hout = (layer == 2) ? g_h2  : g_h3;
    const float* Sin  = (layer == 2) ? g_sldA : g_sldB;
    float*       Sout = (layer == 2) ? g_sldB : g_sldA;

    __shared__ __align__(16) float blob[2 * 2 * 32 * 68];   // 34816 B
    __shared__ float pm[64][4];
    __shared__ float mrow[64];

    float (*As)[32][68] = (float (*)[32][68])(blob);
    float (*Bs)[32][68] = (float (*)[32][68])(blob + 2 * 32 * 68);
    float (*Ps)[68]     = (float (*)[68])(blob);
    float (*wdS)[68]    = (float (*)[68])(blob + 2 * 32 * 68);

    int tid = threadIdx.x;
    int tx = tid & 15, ty = tid >> 4;
    int am = tid >> 2, ak = (tid & 3) * 4;   // A-load map
    int bk = tid >> 4, bn = (tid & 15) * 4;  // B-load map
    int G = gridDim.x;

    for (int r = 0;; r++) {
        int t = r * G + ((r & 1) ? (G - 1 - (int)blockIdx.x) : (int)blockIdx.x);
        if (t >= 256) break;

        int i  = 7 - (t >> 5);
        int n0 = i * 64;
        int m0 = (t & 31) * 64;
        int ntiles = (i + 1) * 2;            // BK=32 tiles (mask skip)

        const float* Aptr = A  + (m0 + am) * 512 + ak;
        const float* Bptr = wT + bk * 512 + n0 + bn;

        float4 a0, a1, b0, b1;
        a0 = *(const float4*)(Aptr);
        a1 = *(const float4*)(Aptr + 16);
        b0 = *(const float4*)(Bptr);
        b1 = *(const float4*)(Bptr + 16 * 512);
        {   // stash into buffer 0
            As[0][ak + 0][am] = a0.x; As[0][ak + 1][am] = a0.y;
            As[0][ak + 2][am] = a0.z; As[0][ak + 3][am] = a0.w;
            As[0][16 + ak + 0][am] = a1.x; As[0][16 + ak + 1][am] = a1.y;
            As[0][16 + ak + 2][am] = a1.z; As[0][16 + ak + 3][am] = a1.w;
            *(float4*)(&Bs[0][bk][bn])      = b0;
            *(float4*)(&Bs[0][bk + 16][bn]) = b1;
        }
        __syncthreads();

        float acc[4][4] = {};

        for (int kt = 0; kt < ntiles; kt++) {
            int cur = kt & 1;
            bool more = (kt + 1 < ntiles);
            if (more) {
                int k0 = (kt + 1) * 32;
                a0 = *(const float4*)(Aptr + k0);
                a1 = *(const float4*)(Aptr + k0 + 16);
                b0 = *(const float4*)(Bptr + k0 * 512);
                b1 = *(const float4*)(Bptr + (k0 + 16) * 512);
            }
            #pragma unroll
            for (int k = 0; k < 32; k++) {
                float4 a  = *(const float4*)(&As[cur][k][ty * 4]);
                float4 bq = *(const float4*)(&Bs[cur][k][tx * 4]);
                acc[0][0] += a.x * bq.x; acc[0][1] += a.x * bq.y;
                acc[0][2] += a.x * bq.z; acc[0][3] += a.x * bq.w;
                acc[1][0] += a.y * bq.x; acc[1][1] += a.y * bq.y;
                acc[1][2] += a.y * bq.z; acc[1][3] += a.y * bq.w;
                acc[2][0] += a.z * bq.x; acc[2][1] += a.z * bq.y;
                acc[2][2] += a.z * bq.z; acc[2][3] += a.z * bq.w;
                acc[3][0] += a.w * bq.x; acc[3][1] += a.w * bq.y;
                acc[3][2] += a.w * bq.z; acc[3][3] += a.w * bq.w;
            }
            if (more) {
                int nxt = cur ^ 1;
                As[nxt][ak + 0][am] = a0.x; As[nxt][ak + 1][am] = a0.y;
                As[nxt][ak + 2][am] = a0.z; As[nxt][ak + 3][am] = a0.w;
                As[nxt][16 + ak + 0][am] = a1.x; As[nxt][16 + ak + 1][am] = a1.y;
                As[nxt][16 + ak + 2][am] = a1.z; As[nxt][16 + ak + 3][am] = a1.w;
                *(float4*)(&Bs[nxt][bk][bn])      = b0;
                *(float4*)(&Bs[nxt][bk + 16][bn]) = b1;
            }
            __syncthreads();
        }
        // blob now free (last sync passed) -> epilogue reuses it as Ps/wdS

        // diag weight block from L2: wdS[j][o] = wT[(i*64+j)*512 + i*64+o]
        for (int idx = tid; idx < 4096; idx += 256) {
            int o = idx & 63, j = idx >> 6;
            wdS[j][o] = wT[(n0 + j) * 512 + n0 + o];
        }

        // sld tile load + row max
        int row = tid >> 2, q = tid & 3;
        const float4* sp = (const float4*)(Sin + (m0 + row) * 512 + n0 + q * 16);
        float4 v4[4];
        float mx = -1e30f;
        #pragma unroll
        for (int c = 0; c < 4; c++) {
            v4[c] = sp[c];
            mx = fmaxf(mx, fmaxf(fmaxf(v4[c].x, v4[c].y), fmaxf(v4[c].z, v4[c].w)));
        }
        pm[row][q] = mx;
        __syncthreads();
        if (tid < 64)
            mrow[tid] = fmaxf(fmaxf(pm[tid][0], pm[tid][1]),
                              fmaxf(pm[tid][2], pm[tid][3]));
        __syncthreads();

        {   // exponentiate into Ps[j][m]
            float m = mrow[row];
            #pragma unroll
            for (int c = 0; c < 4; c++) {
                int j = q * 16 + c * 4;
                Ps[j + 0][row] = expf(v4[c].x - m);
                Ps[j + 1][row] = expf(v4[c].y - m);
                Ps[j + 2][row] = expf(v4[c].z - m);
                Ps[j + 3][row] = expf(v4[c].w - m);
            }
        }
        __syncthreads();

        // mini-GEMM: Q[m][o] = sum_j P[m][j] * wd[o][j]
        float qacc[4][4] = {};
        #pragma unroll 8
        for (int j = 0; j < 64; j++) {
            float4 a  = *(const float4*)(&Ps[j][ty * 4]);
            float4 bq = *(const float4*)(&wdS[j][tx * 4]);
            qacc[0][0] += a.x * bq.x; qacc[0][1] += a.x * bq.y;
            qacc[0][2] += a.x * bq.z; qacc[0][3] += a.x * bq.w;
            qacc[1][0] += a.y * bq.x; qacc[1][1] += a.y * bq.y;
            qacc[1][2] += a.y * bq.z; qacc[1][3] += a.y * bq.w;
            qacc[2][0] += a.z * bq.x; qacc[2][1] += a.z * bq.y;
            qacc[2][2] += a.z * bq.z; qacc[2][3] += a.z * bq.w;
            qacc[3][0] += a.w * bq.x; qacc[3][1] += a.w * bq.y;
            qacc[3][2] += a.w * bq.z; qacc[3][3] += a.w * bq.w;
        }

        // epilogue: h = tanh(y), sld_out in one logf
        #pragma unroll
        for (int ii = 0; ii < 4; ii++) {
            int m = m0 + ty * 4 + ii;
            float mr = mrow[ty * 4 + ii];
            #pragma unroll
            for (int jj = 0; jj < 4; jj++) {
                int n = n0 + tx * 4 + jj;
                float y  = acc[ii][jj] + bias[n];
                float ay = fabsf(y);
                float E  = expf(-2.0f * ay);
                float rc = 1.0f / (1.0f + E);
                Hout[m * 512 + n] = copysignf((1.0f - E) * rc, y);
                Sout[m * 512 + n] = mr + TWO_LN2 - 2.0f * ay
                                  + logf(qacc[ii][jj] * rc * rc);
            }
        }
        __syncthreads();   // guard smem reuse by next item
    }
}

// ---------------------------------------------------------------------------
// fused layer 4: block handles 8 batch rows; w4 cached in smem once.
// warp i handles data dim i: 512-dot + tanh -> out[0:16384]; sld finale ->
// out[16384:32768].
// ---------------------------------------------------------------------------
__global__ void layer_last_kernel(const float* __restrict__ bias,
                                  float* __restrict__ out) {
    __shared__ float wsm[8 * 512];
    int tid = threadIdx.x;
    for (int idx = tid; idx < 4096; idx += 256) wsm[idx] = g_w4n[idx];
    __syncthreads();

    int i = tid >> 5, lane = tid & 31;
    float bz = bias[i];
    float wd0 = wsm[i * 512 + i * 64 + lane];
    float wd1 = wsm[i * 512 + i * 64 + lane + 32];

    int b0 = blockIdx.x * 8;
    #pragma unroll
    for (int r = 0; r < 8; r++) {
        int b = b0 + r;
        const float* hp = g_h3 + b * 512;
        float acc = 0.0f;
        #pragma unroll 4
        for (int k = lane; k < 512; k += 32) acc += hp[k] * wsm[i * 512 + k];
        #pragma unroll
        for (int off = 16; off; off >>= 1)
            acc += __shfl_xor_sync(0xffffffffu, acc, off);

        float y  = acc + bz;
        float ay = fabsf(y);
        float E  = expf(-2.0f * ay);
        float rc = 1.0f / (1.0f + E);

        const float* sp = g_sldA + b * 512 + i * 64;
        float s0 = sp[lane], s1 = sp[lane + 32];
        float m = fmaxf(s0, s1);
        #pragma unroll
        for (int off = 16; off; off >>= 1)
            m = fmaxf(m, __shfl_xor_sync(0xffffffffu, m, off));
        float p0 = expf(s0 - m), p1 = expf(s1 - m);
        float a = p0 * wd0 + p1 * wd1;
        #pragma unroll
        for (int off = 16; off; off >>= 1)
            a += __shfl_xor_sync(0xffffffffu, a, off);

        if (lane == 0) {
            out[b * 8 + i]           = copysignf((1.0f - E) * rc, y);
            out[B_ * D_ + b * 8 + i] = m + TWO_LN2 - 2.0f * ay + logf(a * rc * rc);
        }
    }
}

// ---------------------------------------------------------------------------
extern "C" void kernel_launch(void* const* d_in, const int* in_sizes, int n_in,
                              void* d_out, int out_size) {
    (void)in_sizes; (void)n_in; (void)out_size;
    const float* x  = (const float*)d_in[0];
    const float* W1 = (const float*)d_in[1];
    const float* g1 = (const float*)d_in[2];
    const float* b1 = (const float*)d_in[3];
    const float* W2 = (const float*)d_in[4];
    const float* g2 = (const float*)d_in[5];
    const float* b2 = (const float*)d_in[6];
    const float* W3 = (const float*)d_in[7];
    const float* g3 = (const float*)d_in[8];
    const float* b3 = (const float*)d_in[9];
    const float* W4 = (const float*)d_in[10];
    const float* g4 = (const float*)d_in[11];
    const float* b4 = (const float*)d_in[12];
    float* out = (float*)d_out;

    prep_all_kernel<<<193, dim3(32, 8)>>>(W1, g1, W2, g2, W3, g3, W4, g4);
    gemm1_kernel<<<256, 512>>>(x, b1);
    layer_mid_kernel<<<NSM, 256>>>(2, b2);
    layer_mid_kernel<<<NSM, 256>>>(3, b3);
    layer_last_kernel<<<256, 256>>>(b4, out);
}